// round 11
// baseline (speedup 1.0000x reference)
#include <cuda_runtime.h>
#include <cstdint>
#include <cmath>

// Problem constants (fixed by the dataset)
#define T_TOK 1024
#define H_DIM 2048
#define I_DIM 768
#define E_NUM 8
#define K_TOP 2
#define NROWS (T_TOK * K_TOP)      // 2048 permuted rows

#define BM 96                      // CTA M-tile (both gemms)
#define MAX_TILES 32               // sum_e ceil(cnt_e/96) <= 29

// ---------------- scratch (no allocations allowed) ----------------
__device__ int   g_row_src[NROWS];
__device__ int   g_pos[NROWS];
__device__ int   g_tile_expert[MAX_TILES];
__device__ int   g_tile_row[MAX_TILES];
__device__ int   g_tile_end[MAX_TILES];
__device__ int   g_num_tiles;
__device__ float g_xc[T_TOK * H_DIM];     // tf32-rounded hidden_states
__device__ float g_act[NROWS * I_DIM];    // tf32-rounded swiglu output
__device__ float g_fc2[NROWS * H_DIM];

// ---------------- PTX helpers (all sm_80-level, no 'a' features) ----------------
__device__ __forceinline__ uint32_t s2u(const void* p) {
    uint32_t a;
    asm("{ .reg .u64 t; cvta.to.shared.u64 t, %1; cvt.u32.u64 %0, t; }" : "=r"(a) : "l"(p));
    return a;
}
__device__ __forceinline__ void cp16(uint32_t dst, const void* src, uint32_t sz) {
    asm volatile("cp.async.cg.shared.global [%0], [%1], 16, %2;" :: "r"(dst), "l"(src), "r"(sz));
}
__device__ __forceinline__ void cp_commit() { asm volatile("cp.async.commit_group;" ::: "memory"); }
template<int N> __device__ __forceinline__ void cp_wait() {
    asm volatile("cp.async.wait_group %0;" :: "n"(N) : "memory");
}
__device__ __forceinline__ void bar_sync(int id, int cnt) {
    asm volatile("bar.sync %0, %1;" :: "r"(id), "r"(cnt) : "memory");
}
__device__ __forceinline__ void bar_arrive(int id, int cnt) {
    asm volatile("bar.arrive %0, %1;" :: "r"(id), "r"(cnt) : "memory");
}
__device__ __forceinline__ void ldsm4(uint32_t r[4], uint32_t addr) {
    asm volatile("ldmatrix.sync.aligned.m8n8.x4.shared.b16 {%0,%1,%2,%3}, [%4];"
        : "=r"(r[0]), "=r"(r[1]), "=r"(r[2]), "=r"(r[3]) : "r"(addr));
}
__device__ __forceinline__ uint32_t f2tf_f(float x) {
    uint32_t r;
    asm("cvt.rna.tf32.f32 %0, %1;" : "=r"(r) : "f"(x));
    return r;
}
__device__ __forceinline__ float tfr(float x) {
    return __uint_as_float(f2tf_f(x));
}
__device__ __forceinline__ void mma8(float* c, const uint32_t* a, uint32_t b0, uint32_t b1) {
    asm volatile(
        "mma.sync.aligned.m16n8k8.row.col.f32.tf32.tf32.f32 "
        "{%0,%1,%2,%3}, {%4,%5,%6,%7}, {%8,%9}, {%0,%1,%2,%3};"
        : "+f"(c[0]), "+f"(c[1]), "+f"(c[2]), "+f"(c[3])
        : "r"(a[0]), "r"(a[1]), "r"(a[2]), "r"(a[3]), "r"(b0), "r"(b1));
}

// Stage: A 96x32f (128B rows, XOR swizzle) = 12288B ; B 32 x 136f = 17408B
#define STG 29696
#define SMEM_TOTAL 89088           // 3 stages; 2 CTAs/SM (2*(89088+1024) < 228KB)
#define BPAD 136

// Named barriers: FULL[pair 0..2][stage 0..2] ids 1..9 (count 128)
//                 FREE[stage] ids 10..12 (count 256)
#define BFULL(p, s) (1 + (p) * 3 + (s))
#define BFREE(s)    (10 + (s))

// ---------------- setup: counting sort + BM=96 tiling ----------------
__global__ void setup_kernel(const int* __restrict__ sel) {
    __shared__ int cnt[E_NUM];
    __shared__ int run[E_NUM];
    int tid = threadIdx.x;
    if (tid < E_NUM) cnt[tid] = 0;
    __syncthreads();
    for (int i = tid; i < NROWS; i += blockDim.x)
        atomicAdd(&cnt[sel[i]], 1);
    __syncthreads();
    if (tid == 0) {
        int s = 0, nt = 0;
        for (int e = 0; e < E_NUM; e++) {
            run[e] = s;
            int c = cnt[e];
            for (int r = 0; r < c; r += BM) {
                g_tile_expert[nt] = e;
                g_tile_row[nt]    = s + r;
                g_tile_end[nt]    = s + c;
                nt++;
            }
            s += c;
        }
        g_num_tiles = nt;
    }
    __syncthreads();
    for (int i = tid; i < NROWS; i += blockDim.x) {
        int e = sel[i];
        int p = atomicAdd(&run[e], 1);
        g_row_src[p] = i;
        g_pos[i] = p;
    }
}

// ---------------- cvtx: g_xc = tf32(x) ----------------
__global__ void __launch_bounds__(256)
cvtx_kernel(const float* __restrict__ x) {
    int i = blockIdx.x * blockDim.x + threadIdx.x;
    if (i >= T_TOK * (H_DIM / 4)) return;
    float4 v = reinterpret_cast<const float4*>(x)[i];
    v.x = tfr(v.x); v.y = tfr(v.y); v.z = tfr(v.z); v.w = tfr(v.w);
    reinterpret_cast<float4*>(g_xc)[i] = v;
}

// ---------------- GEMM1: act = swiglu( Xc_gather @ W1[e] ) ----------------
// Tile 96 x (gate64+up64). Warps 0-5 consumers (3x2, warp 32x(32g+32u)), 6-7 producers.
__global__ void __launch_bounds__(256, 2)
gemm1_kernel(const float* __restrict__ w1) {
    extern __shared__ char smem[];
    uint32_t sb = s2u(smem);
    int mt = blockIdx.x;
    if (mt >= g_num_tiles) return;
    int e = g_tile_expert[mt], row0 = g_tile_row[mt], rend = g_tile_end[mt];
    int col0g = blockIdx.y * 64;

    int tid = threadIdx.x, lane = tid & 31, wid = tid >> 5;
    const float* W = w1 + (size_t)e * H_DIM * (2 * I_DIM);
    const int NC = H_DIM / 32;     // 64 chunks

    if (wid >= 6) {
        // ================= PRODUCER (warps 6,7) =================
        int p = (wid - 6) * 32 + lane;         // 0..63
        int tokq[12];
        uint32_t szq[12];
        #pragma unroll
        for (int q = 0; q < 12; q++) {
            int row = (p + 64 * q) >> 3;
            int r = row0 + row;
            int t = (r < rend) ? (g_row_src[r] / K_TOP) : -1;
            tokq[q] = (t < 0) ? 0 : t;
            szq[q]  = (t < 0) ? 0u : 16u;
        }
        for (int c = 0; c < NC; c++) {
            int s = c % 3;
            if (c >= 3) bar_sync(BFREE(s), 256);
            uint32_t Ab = sb + s * STG;
            uint32_t Bb = Ab + 12288;
            int k0 = c * 32;
            #pragma unroll
            for (int q = 0; q < 12; q++) {
                int idx = p + 64 * q;
                int row = idx >> 3, c16 = idx & 7;
                cp16(Ab + row * 128 + ((c16 ^ (row & 7)) << 4),
                     g_xc + (size_t)tokq[q] * H_DIM + k0 + c16 * 4, szq[q]);
            }
            #pragma unroll
            for (int q = 0; q < 16; q++) {
                int idx = p + 64 * q;
                int k = idx >> 5, n = (idx & 31) * 4;
                const float* src = (n < 64)
                    ? W + (size_t)(k0 + k) * (2 * I_DIM) + col0g + n
                    : W + (size_t)(k0 + k) * (2 * I_DIM) + I_DIM + col0g + (n - 64);
                cp16(Bb + k * (BPAD * 4) + n * 4, src, 16);
            }
            cp_commit();
            if (c >= 2) {
                cp_wait<2>();
                int s2 = (c - 2) % 3;
                bar_arrive(BFULL(0, s2), 128);
                bar_arrive(BFULL(1, s2), 128);
                bar_arrive(BFULL(2, s2), 128);
            }
        }
        cp_wait<1>();
        { int s2 = (NC - 2) % 3;
          bar_arrive(BFULL(0, s2), 128); bar_arrive(BFULL(1, s2), 128); bar_arrive(BFULL(2, s2), 128); }
        cp_wait<0>();
        { int s2 = (NC - 1) % 3;
          bar_arrive(BFULL(0, s2), 128); bar_arrive(BFULL(1, s2), 128); bar_arrive(BFULL(2, s2), 128); }
        return;
    }

    // ================= CONSUMER (warps 0-5) =================
    int pr    = wid >> 1;           // pair index / warpM (0..2)
    int warpM = wid >> 1;
    int warpN = wid & 1;
    int gid = lane >> 2, tig = lane & 3;
    int mlane = lane & 15, extra = lane >> 4, key = lane & 7;

    int boffG = tig * BPAD + warpN * 32 + gid;
    int boffU = boffG + 64;

    float accG[2][4][4] = {}, accU[2][4][4] = {};
    for (int i = 0; i < NC; i++) {
        int s = i % 3;
        bar_sync(BFULL(pr, s), 128);
        uint32_t Ab = sb + s * STG;
        const float* Bsp = (const float*)(smem + s * STG + 12288);
        #pragma unroll
        for (int ks = 0; ks < 4; ks++) {
            uint32_t af[2][4];
            #pragma unroll
            for (int mi = 0; mi < 2; mi++) {
                uint32_t addr = Ab + (uint32_t)((warpM * 32 + mi * 16 + mlane) * 128
                              + ((((ks << 1) | extra) ^ key) << 4));
                ldsm4(af[mi], addr);
            }
            #pragma unroll
            for (int j = 0; j < 4; j++) {
                uint32_t g0 = f2tf_f(Bsp[boffG + ks * (8 * BPAD) + j * 8]);
                uint32_t g1 = f2tf_f(Bsp[boffG + ks * (8 * BPAD) + j * 8 + 4 * BPAD]);
                uint32_t u0 = f2tf_f(Bsp[boffU + ks * (8 * BPAD) + j * 8]);
                uint32_t u1 = f2tf_f(Bsp[boffU + ks * (8 * BPAD) + j * 8 + 4 * BPAD]);
                #pragma unroll
                for (int mi = 0; mi < 2; mi++) {
                    mma8(accG[mi][j], af[mi], g0, g1);
                    mma8(accU[mi][j], af[mi], u0, u1);
                }
            }
        }
        bar_arrive(BFREE(s), 256);
    }

    // epilogue: register swiglu -> g_act (tf32-rounded)
    #pragma unroll
    for (int mi = 0; mi < 2; mi++) {
        #pragma unroll
        for (int j = 0; j < 4; j++) {
            int row = row0 + warpM * 32 + mi * 16 + gid;
            int col = col0g + warpN * 32 + j * 8 + 2 * tig;
            float g0 = accG[mi][j][0], g1 = accG[mi][j][1];
            float u0 = accU[mi][j][0], u1 = accU[mi][j][1];
            float g2 = accG[mi][j][2], g3 = accG[mi][j][3];
            float u2 = accU[mi][j][2], u3 = accU[mi][j][3];
            if (row < rend) {
                float2 o;
                o.x = tfr(g0 * (1.0f / (1.0f + __expf(-g0))) * u0);
                o.y = tfr(g1 * (1.0f / (1.0f + __expf(-g1))) * u1);
                *(float2*)&g_act[(size_t)row * I_DIM + col] = o;
            }
            if (row + 8 < rend) {
                float2 o;
                o.x = tfr(g2 * (1.0f / (1.0f + __expf(-g2))) * u2);
                o.y = tfr(g3 * (1.0f / (1.0f + __expf(-g3))) * u3);
                *(float2*)&g_act[(size_t)(row + 8) * I_DIM + col] = o;
            }
        }
    }
}

// ---------------- GEMM2: fc2 = act @ W2[e] ----------------
// Tile 96 x 128. Warps 0-5 consumers (3x2, warp 32x64), 6-7 producers.
__global__ void __launch_bounds__(256, 2)
gemm2_kernel(const float* __restrict__ w2) {
    extern __shared__ char smem[];
    uint32_t sb = s2u(smem);
    int mt = blockIdx.x;
    if (mt >= g_num_tiles) return;
    int e = g_tile_expert[mt], row0 = g_tile_row[mt], rend = g_tile_end[mt];
    int col0 = blockIdx.y * 128;

    int tid = threadIdx.x, lane = tid & 31, wid = tid >> 5;
    const float* W = w2 + (size_t)e * I_DIM * H_DIM;
    const int NC = I_DIM / 32;     // 24 chunks

    if (wid >= 6) {
        // ================= PRODUCER (warps 6,7) =================
        int p = (wid - 6) * 32 + lane;
        const float* aq[12];
        #pragma unroll
        for (int q = 0; q < 12; q++) {
            int row = (p + 64 * q) >> 3;
            int r = row0 + row;
            if (r >= NROWS) r = NROWS - 1;      // clamp; masked in epilogue
            aq[q] = g_act + (size_t)r * I_DIM;
        }
        for (int c = 0; c < NC; c++) {
            int s = c % 3;
            if (c >= 3) bar_sync(BFREE(s), 256);
            uint32_t Ab = sb + s * STG;
            uint32_t Bb = Ab + 12288;
            int k0 = c * 32;
            #pragma unroll
            for (int q = 0; q < 12; q++) {
                int idx = p + 64 * q;
                int row = idx >> 3, c16 = idx & 7;
                cp16(Ab + row * 128 + ((c16 ^ (row & 7)) << 4), aq[q] + k0 + c16 * 4, 16);
            }
            #pragma unroll
            for (int q = 0; q < 16; q++) {
                int idx = p + 64 * q;
                int k = idx >> 5, n = (idx & 31) * 4;
                cp16(Bb + k * (BPAD * 4) + n * 4, W + (size_t)(k0 + k) * H_DIM + col0 + n, 16);
            }
            cp_commit();
            if (c >= 2) {
                cp_wait<2>();
                int s2 = (c - 2) % 3;
                bar_arrive(BFULL(0, s2), 128);
                bar_arrive(BFULL(1, s2), 128);
                bar_arrive(BFULL(2, s2), 128);
            }
        }
        cp_wait<1>();
        { int s2 = (NC - 2) % 3;
          bar_arrive(BFULL(0, s2), 128); bar_arrive(BFULL(1, s2), 128); bar_arrive(BFULL(2, s2), 128); }
        cp_wait<0>();
        { int s2 = (NC - 1) % 3;
          bar_arrive(BFULL(0, s2), 128); bar_arrive(BFULL(1, s2), 128); bar_arrive(BFULL(2, s2), 128); }
        return;
    }

    // ================= CONSUMER (warps 0-5) =================
    int pr    = wid >> 1;
    int warpM = wid >> 1;
    int warpN = wid & 1;
    int gid = lane >> 2, tig = lane & 3;
    int mlane = lane & 15, extra = lane >> 4, key = lane & 7;
    int boff = tig * BPAD + warpN * 64 + gid;

    float acc[2][8][4] = {};
    for (int i = 0; i < NC; i++) {
        int s = i % 3;
        bar_sync(BFULL(pr, s), 128);
        uint32_t Ab = sb + s * STG;
        const float* Bsp = (const float*)(smem + s * STG + 12288);
        #pragma unroll
        for (int ks = 0; ks < 4; ks++) {
            uint32_t af[2][4];
            #pragma unroll
            for (int mi = 0; mi < 2; mi++) {
                uint32_t addr = Ab + (uint32_t)((warpM * 32 + mi * 16 + mlane) * 128
                              + ((((ks << 1) | extra) ^ key) << 4));
                ldsm4(af[mi], addr);
            }
            #pragma unroll
            for (int j = 0; j < 8; j++) {
                uint32_t b0 = f2tf_f(Bsp[boff + ks * (8 * BPAD) + j * 8]);
                uint32_t b1 = f2tf_f(Bsp[boff + ks * (8 * BPAD) + j * 8 + 4 * BPAD]);
                #pragma unroll
                for (int mi = 0; mi < 2; mi++)
                    mma8(acc[mi][j], af[mi], b0, b1);
            }
        }
        bar_arrive(BFREE(s), 256);
    }

    // epilogue: direct to g_fc2
    #pragma unroll
    for (int mi = 0; mi < 2; mi++) {
        int row = row0 + warpM * 32 + mi * 16 + gid;
        #pragma unroll
        for (int j = 0; j < 8; j++) {
            int col = col0 + warpN * 64 + j * 8 + 2 * tig;
            if (row < rend)
                *(float2*)&g_fc2[(size_t)row * H_DIM + col] =
                    make_float2(acc[mi][j][0], acc[mi][j][1]);
            if (row + 8 < rend)
                *(float2*)&g_fc2[(size_t)(row + 8) * H_DIM + col] =
                    make_float2(acc[mi][j][2], acc[mi][j][3]);
        }
    }
}

// ---------------- combine ----------------
__global__ void __launch_bounds__(256)
combine_kernel(const float* __restrict__ rw, float* __restrict__ out) {
    int i = blockIdx.x * blockDim.x + threadIdx.x;
    if (i >= T_TOK * (H_DIM / 4)) return;
    int t  = i >> 9;
    int h4 = i & 511;
    int p0 = g_pos[2 * t];
    int p1 = g_pos[2 * t + 1];
    float w0 = rw[2 * t];
    float w1 = rw[2 * t + 1];
    float4 v0 = *reinterpret_cast<const float4*>(&g_fc2[(size_t)p0 * H_DIM + h4 * 4]);
    float4 v1 = *reinterpret_cast<const float4*>(&g_fc2[(size_t)p1 * H_DIM + h4 * 4]);
    float4 o;
    o.x = w0 * v0.x + w1 * v1.x;
    o.y = w0 * v0.y + w1 * v1.y;
    o.z = w0 * v0.z + w1 * v1.z;
    o.w = w0 * v0.w + w1 * v1.w;
    reinterpret_cast<float4*>(out)[i] = o;
}

// ---------------- launch ----------------
extern "C" void kernel_launch(void* const* d_in, const int* in_sizes, int n_in,
                              void* d_out, int out_size) {
    const float* x   = (const float*)d_in[0];   // hidden_states [T, H]
    const float* rw  = (const float*)d_in[1];   // routing_weights [T, K]
    const float* w1  = (const float*)d_in[2];   // gate_up_proj [E, H, 2I]
    const float* w2  = (const float*)d_in[3];   // down_proj   [E, I, H]
    const int*   sel = (const int*)d_in[4];     // selected_experts [T, K]
    float* out = (float*)d_out;                 // [T, H] fp32

    cudaFuncSetAttribute(gemm1_kernel, cudaFuncAttributeMaxDynamicSharedMemorySize, SMEM_TOTAL);
    cudaFuncSetAttribute(gemm2_kernel, cudaFuncAttributeMaxDynamicSharedMemorySize, SMEM_TOTAL);

    setup_kernel<<<1, 256>>>(sel);
    cvtx_kernel<<<(T_TOK * H_DIM / 4 + 255) / 256, 256>>>(x);
    gemm1_kernel<<<dim3(MAX_TILES, I_DIM / 64), 256, SMEM_TOTAL>>>(w1);
    gemm2_kernel<<<dim3(MAX_TILES, H_DIM / 128), 256, SMEM_TOTAL>>>(w2);
    combine_kernel<<<(T_TOK * H_DIM / 4 + 255) / 256, 256>>>(rw, out);
}

// round 12
// speedup vs baseline: 1.0350x; 1.0350x over previous
#include <cuda_runtime.h>
#include <cstdint>
#include <cmath>

// Problem constants (fixed by the dataset)
#define T_TOK 1024
#define H_DIM 2048
#define I_DIM 768
#define E_NUM 8
#define K_TOP 2
#define NROWS (T_TOK * K_TOP)      // 2048 permuted rows

#define BM 128
#define MAX_TILES 24               // sum_e ceil(cnt_e/128) <= 24

// ---------------- scratch (no allocations allowed) ----------------
__device__ int   g_row_src[NROWS];
__device__ int   g_pos[NROWS];
__device__ int   g_tile_expert[MAX_TILES];
__device__ int   g_tile_row[MAX_TILES];
__device__ int   g_tile_end[MAX_TILES];
__device__ int   g_num_tiles;
__device__ float g_xc[T_TOK * H_DIM];           // tf32-rounded hidden_states
__device__ float g_act[NROWS * I_DIM];          // tf32-rounded swiglu output
__device__ float g_fc1h0[NROWS * 2 * I_DIM];    // fc1 K-half 0
__device__ float g_fc1h1[NROWS * 2 * I_DIM];    // fc1 K-half 1
__device__ float g_fc2h0[NROWS * H_DIM];        // fc2 K-half 0
__device__ float g_fc2h1[NROWS * H_DIM];        // fc2 K-half 1

// ---------------- PTX helpers (all sm_80-level, no 'a' features) ----------------
__device__ __forceinline__ uint32_t s2u(const void* p) {
    uint32_t a;
    asm("{ .reg .u64 t; cvta.to.shared.u64 t, %1; cvt.u32.u64 %0, t; }" : "=r"(a) : "l"(p));
    return a;
}
__device__ __forceinline__ void cp16(uint32_t dst, const void* src, uint32_t sz) {
    asm volatile("cp.async.cg.shared.global [%0], [%1], 16, %2;" :: "r"(dst), "l"(src), "r"(sz));
}
__device__ __forceinline__ void cp_commit() { asm volatile("cp.async.commit_group;" ::: "memory"); }
template<int N> __device__ __forceinline__ void cp_wait() {
    asm volatile("cp.async.wait_group %0;" :: "n"(N) : "memory");
}
__device__ __forceinline__ void ldsm4(uint32_t r[4], uint32_t addr) {
    asm volatile("ldmatrix.sync.aligned.m8n8.x4.shared.b16 {%0,%1,%2,%3}, [%4];"
        : "=r"(r[0]), "=r"(r[1]), "=r"(r[2]), "=r"(r[3]) : "r"(addr));
}
__device__ __forceinline__ uint32_t f2tf_f(float x) {
    uint32_t r;
    asm("cvt.rna.tf32.f32 %0, %1;" : "=r"(r) : "f"(x));
    return r;
}
__device__ __forceinline__ float tfr(float x) {
    return __uint_as_float(f2tf_f(x));
}
__device__ __forceinline__ void mma8(float* c, const uint32_t* a, uint32_t b0, uint32_t b1) {
    asm volatile(
        "mma.sync.aligned.m16n8k8.row.col.f32.tf32.tf32.f32 "
        "{%0,%1,%2,%3}, {%4,%5,%6,%7}, {%8,%9}, {%0,%1,%2,%3};"
        : "+f"(c[0]), "+f"(c[1]), "+f"(c[2]), "+f"(c[3])
        : "r"(a[0]), "r"(a[1]), "r"(a[2]), "r"(a[3]), "r"(b0), "r"(b1));
}

// SMEM: 3 stages of {A 16KB (128x32f swizzled), B 17408B (32 x 136 f)}
#define BPAD 136
#define STG 33792
#define SMEM_TOTAL 101376
#define OFF_A(b) ((b) * STG)
#define OFF_B(b) (OFF_A(b) + 16384)

// ---------------- setup: counting sort + BM=128 tiling ----------------
__global__ void setup_kernel(const int* __restrict__ sel) {
    __shared__ int cnt[E_NUM];
    __shared__ int run[E_NUM];
    int tid = threadIdx.x;
    if (tid < E_NUM) cnt[tid] = 0;
    __syncthreads();
    for (int i = tid; i < NROWS; i += blockDim.x)
        atomicAdd(&cnt[sel[i]], 1);
    __syncthreads();
    if (tid == 0) {
        int s = 0, nt = 0;
        for (int e = 0; e < E_NUM; e++) {
            run[e] = s;
            int c = cnt[e];
            for (int r = 0; r < c; r += BM) {
                g_tile_expert[nt] = e;
                g_tile_row[nt]    = s + r;
                g_tile_end[nt]    = s + c;
                nt++;
            }
            s += c;
        }
        g_num_tiles = nt;
    }
    __syncthreads();
    for (int i = tid; i < NROWS; i += blockDim.x) {
        int e = sel[i];
        int p = atomicAdd(&run[e], 1);
        g_row_src[p] = i;
        g_pos[i] = p;
    }
}

// ---------------- cvtx: g_xc = tf32(x) ----------------
__global__ void __launch_bounds__(256)
cvtx_kernel(const float* __restrict__ x) {
    int i = blockIdx.x * blockDim.x + threadIdx.x;
    if (i >= T_TOK * (H_DIM / 4)) return;
    float4 v = reinterpret_cast<const float4*>(x)[i];
    v.x = tfr(v.x); v.y = tfr(v.y); v.z = tfr(v.z); v.w = tfr(v.w);
    reinterpret_cast<float4*>(g_xc)[i] = v;
}

// ---------------- unified split-K grouped GEMM ----------------
// MODE 0: fc1_half[z] = Xc_gather @ W1[e][kz-half]   (out width 1536)
// MODE 1: fc2_half[z] = act @ W2[e][kz-half]         (out width 2048)
// Tile 128x128, 8 warps (2x4), warp 64x32, 3-stage cp.async, ks-staggered.
template<int MODE>
__global__ void __launch_bounds__(256, 2)
gemm_kernel(const float* __restrict__ Wall) {
    constexpr int LDW = MODE ? H_DIM : 2 * I_DIM;         // 2048 : 1536
    constexpr int KH  = MODE ? (I_DIM / 2) : (H_DIM / 2); // 384 : 1024
    constexpr int NCH = KH / 32;                          // 12 : 32
    constexpr size_t ESTR = MODE ? (size_t)I_DIM * H_DIM : (size_t)H_DIM * 2 * I_DIM;

    extern __shared__ char smem[];
    uint32_t sb = s2u(smem);
    int mt = blockIdx.x;
    if (mt >= g_num_tiles) return;
    int e = g_tile_expert[mt], row0 = g_tile_row[mt], rend = g_tile_end[mt];
    int col0 = blockIdx.y * 128;
    int kz = blockIdx.z;

    int tid = threadIdx.x, lane = tid & 31, wid = tid >> 5;
    int warpM = wid >> 2, warpN = wid & 3;
    int gid = lane >> 2, tig = lane & 3;

    const float* W = Wall + (size_t)e * ESTR + (size_t)(kz * KH) * LDW + col0;

    // A loader: row am (0..127), one float4x4 sweep at 16B-units (XOR swizzle)
    int am = tid >> 1;
    int ac0 = (tid & 1) * 4;
    int akey = am & 7;
    const float* asrc;
    uint32_t asz;
    if (MODE == 0) {
        int r = row0 + am;
        int tok = (r < rend) ? (g_row_src[r] / K_TOP) : -1;
        asrc = g_xc + (size_t)(tok < 0 ? 0 : tok) * H_DIM + kz * KH;
        asz  = (tok < 0) ? 0u : 16u;
    } else {
        int rr = row0 + am; if (rr >= NROWS) rr = NROWS - 1;
        asrc = g_act + (size_t)rr * I_DIM + kz * KH;
        asz  = 16u;
    }

    auto load_chunk = [&](int ci, int buf) {
        int k0 = ci * 32;
        uint32_t Ab = sb + OFF_A(buf);
        #pragma unroll
        for (int c = 0; c < 4; c++) {
            int cc = ac0 + c;
            cp16(Ab + am * 128 + ((cc ^ akey) << 4), asrc + k0 + cc * 4, asz);
        }
        uint32_t Bb = sb + OFF_B(buf);
        #pragma unroll
        for (int it = 0; it < 4; it++) {
            int q = tid + it * 256;
            int k = q >> 5, n = (q & 31) * 4;
            cp16(Bb + k * (BPAD * 4) + n * 4, W + (size_t)(k0 + k) * LDW + n, 16);
        }
        cp_commit();
    };

    int mlane = lane & 15, extra = lane >> 4, key = lane & 7;
    int boff = tig * BPAD + warpN * 32 + gid;
    int ph = 2 * warpM;

    float acc[4][4][4] = {};
    load_chunk(0, 0);
    load_chunk(1, 1);
    int bc = 0;
    for (int i = 0; i < NCH; i++) {
        cp_wait<1>();
        __syncthreads();
        int bn = bc + 2; if (bn >= 3) bn -= 3;
        if (i + 2 < NCH) load_chunk(i + 2, bn);
        else             cp_commit();

        uint32_t Ab = sb + OFF_A(bc);
        const float* Bsp = (const float*)(smem + OFF_B(bc));
        #pragma unroll
        for (int ks = 0; ks < 4; ks++) {
            int kse = (ks + ph) & 3;
            uint32_t a[4][4];
            #pragma unroll
            for (int mi = 0; mi < 4; mi++) {
                uint32_t addr = Ab + (uint32_t)((warpM * 64 + mi * 16 + mlane) * 128
                              + ((((kse << 1) | extra) ^ key) << 4));
                ldsm4(a[mi], addr);
            }
            #pragma unroll
            for (int j = 0; j < 4; j++) {
                uint32_t b0 = f2tf_f(Bsp[boff + kse * (8 * BPAD) + j * 8]);
                uint32_t b1 = f2tf_f(Bsp[boff + kse * (8 * BPAD) + j * 8 + 4 * BPAD]);
                #pragma unroll
                for (int mi = 0; mi < 4; mi++)
                    mma8(acc[mi][j], a[mi], b0, b1);
            }
        }
        bc = (bc + 1 == 3) ? 0 : bc + 1;
    }

    // epilogue: plain stores into this K-half's buffer
    float* outb = MODE ? (kz ? g_fc2h1 : g_fc2h0) : (kz ? g_fc1h1 : g_fc1h0);
    #pragma unroll
    for (int mi = 0; mi < 4; mi++) {
        int row = row0 + warpM * 64 + mi * 16 + gid;
        #pragma unroll
        for (int j = 0; j < 4; j++) {
            int col = col0 + warpN * 32 + j * 8 + 2 * tig;
            if (row < rend)
                *(float2*)&outb[(size_t)row * LDW + col] =
                    make_float2(acc[mi][j][0], acc[mi][j][1]);
            if (row + 8 < rend)
                *(float2*)&outb[(size_t)(row + 8) * LDW + col] =
                    make_float2(acc[mi][j][2], acc[mi][j][3]);
        }
    }
}

// ---------------- swiglu: g_act = tf32(swiglu(fc1h0 + fc1h1)) ----------------
__global__ void __launch_bounds__(256)
swiglu_kernel() {
    int i = blockIdx.x * blockDim.x + threadIdx.x;   // over NROWS * I_DIM/4
    if (i >= NROWS * (I_DIM / 4)) return;
    int r = i / (I_DIM / 4);
    int c = (i % (I_DIM / 4)) * 4;
    size_t base = (size_t)r * (2 * I_DIM) + c;
    float4 ga = *(float4*)&g_fc1h0[base];
    float4 gb = *(float4*)&g_fc1h1[base];
    float4 ua = *(float4*)&g_fc1h0[base + I_DIM];
    float4 ub = *(float4*)&g_fc1h1[base + I_DIM];
    float g[4] = { ga.x + gb.x, ga.y + gb.y, ga.z + gb.z, ga.w + gb.w };
    float u[4] = { ua.x + ub.x, ua.y + ub.y, ua.z + ub.z, ua.w + ub.w };
    float4 o;
    float* op = (float*)&o;
    #pragma unroll
    for (int jj = 0; jj < 4; jj++)
        op[jj] = tfr(g[jj] * (1.0f / (1.0f + __expf(-g[jj]))) * u[jj]);
    *(float4*)&g_act[(size_t)r * I_DIM + c] = o;
}

// ---------------- combine: out[t] = w0*(fc2h0+fc2h1)[p0] + w1*(...)[p1] ----------------
__global__ void __launch_bounds__(256)
combine_kernel(const float* __restrict__ rw, float* __restrict__ out) {
    int i = blockIdx.x * blockDim.x + threadIdx.x;
    if (i >= T_TOK * (H_DIM / 4)) return;
    int t  = i >> 9;
    int h4 = i & 511;
    int p0 = g_pos[2 * t];
    int p1 = g_pos[2 * t + 1];
    float w0 = rw[2 * t];
    float w1 = rw[2 * t + 1];
    size_t o0 = (size_t)p0 * H_DIM + h4 * 4;
    size_t o1 = (size_t)p1 * H_DIM + h4 * 4;
    float4 a0 = *(const float4*)&g_fc2h0[o0];
    float4 b0 = *(const float4*)&g_fc2h1[o0];
    float4 a1 = *(const float4*)&g_fc2h0[o1];
    float4 b1 = *(const float4*)&g_fc2h1[o1];
    float4 o;
    o.x = w0 * (a0.x + b0.x) + w1 * (a1.x + b1.x);
    o.y = w0 * (a0.y + b0.y) + w1 * (a1.y + b1.y);
    o.z = w0 * (a0.z + b0.z) + w1 * (a1.z + b1.z);
    o.w = w0 * (a0.w + b0.w) + w1 * (a1.w + b1.w);
    reinterpret_cast<float4*>(out)[i] = o;
}

// ---------------- launch ----------------
extern "C" void kernel_launch(void* const* d_in, const int* in_sizes, int n_in,
                              void* d_out, int out_size) {
    const float* x   = (const float*)d_in[0];   // hidden_states [T, H]
    const float* rw  = (const float*)d_in[1];   // routing_weights [T, K]
    const float* w1  = (const float*)d_in[2];   // gate_up_proj [E, H, 2I]
    const float* w2  = (const float*)d_in[3];   // down_proj   [E, I, H]
    const int*   sel = (const int*)d_in[4];     // selected_experts [T, K]
    float* out = (float*)d_out;                 // [T, H] fp32

    cudaFuncSetAttribute(gemm_kernel<0>, cudaFuncAttributeMaxDynamicSharedMemorySize, SMEM_TOTAL);
    cudaFuncSetAttribute(gemm_kernel<1>, cudaFuncAttributeMaxDynamicSharedMemorySize, SMEM_TOTAL);

    setup_kernel<<<1, 256>>>(sel);
    cvtx_kernel<<<(T_TOK * H_DIM / 4 + 255) / 256, 256>>>(x);
    gemm_kernel<0><<<dim3(MAX_TILES, (2 * I_DIM) / 128, 2), 256, SMEM_TOTAL>>>(w1);
    swiglu_kernel<<<(NROWS * (I_DIM / 4) + 255) / 256, 256>>>();
    gemm_kernel<1><<<dim3(MAX_TILES, H_DIM / 128, 2), 256, SMEM_TOTAL>>>(w2);
    combine_kernel<<<(T_TOK * H_DIM / 4 + 255) / 256, 256>>>(rw, out);
}